// round 11
// baseline (speedup 1.0000x reference)
#include <cuda_runtime.h>

// Scratch for per-row hinge values (no device allocation allowed).
// B = 16384 for this problem; sized with headroom.
__device__ float g_partials[32768];

#define MARGIN 1.0f
#define EPS 1e-6f

// One warp per row. Each lane strides over D/4 float4's (D=1024 -> 8 iters).
__global__ void hinge_rows_kernel(const float* __restrict__ out,
                                  const float* __restrict__ tgt,
                                  const long long* __restrict__ neg,
                                  float* __restrict__ partials,
                                  int B, int D)
{
    int gwarp = (blockIdx.x * blockDim.x + threadIdx.x) >> 5;
    int lane  = threadIdx.x & 31;
    if (gwarp >= B) return;

    const int i = gwarp;
    long long j = ((long long)i + 1 + neg[i]) % (long long)B;

    const float4* __restrict__ o4 = (const float4*)(out + (size_t)i * D);
    const float4* __restrict__ t4 = (const float4*)(tgt + (size_t)i * D);
    const float4* __restrict__ n4 = (const float4*)(tgt + (size_t)j * D);

    float dp = 0.f;   // dot(o, t_pos)
    float dn = 0.f;   // dot(o, t_neg)
    float no = 0.f;   // ||o||^2
    float nt = 0.f;   // ||t_pos||^2
    float nn = 0.f;   // ||t_neg||^2

    const int nv = D >> 2;   // float4 count per row
    #pragma unroll 8
    for (int k = lane; k < nv; k += 32) {
        float4 o = o4[k];
        float4 t = t4[k];
        float4 g = n4[k];
        dp += o.x * t.x + o.y * t.y + o.z * t.z + o.w * t.w;
        dn += o.x * g.x + o.y * g.y + o.z * g.z + o.w * g.w;
        no += o.x * o.x + o.y * o.y + o.z * o.z + o.w * o.w;
        nt += t.x * t.x + t.y * t.y + t.z * t.z + t.w * t.w;
        nn += g.x * g.x + g.y * g.y + g.z * g.z + g.w * g.w;
    }

    // Warp tree reduction for the 5 accumulators.
    #pragma unroll
    for (int off = 16; off > 0; off >>= 1) {
        dp += __shfl_xor_sync(0xFFFFFFFFu, dp, off);
        dn += __shfl_xor_sync(0xFFFFFFFFu, dn, off);
        no += __shfl_xor_sync(0xFFFFFFFFu, no, off);
        nt += __shfl_xor_sync(0xFFFFFFFFu, nt, off);
        nn += __shfl_xor_sync(0xFFFFFFFFu, nn, off);
    }

    if (lane == 0) {
        float norm_o = sqrtf(no);
        float den_p  = fmaxf(sqrtf(nt) * norm_o, EPS);
        float den_n  = fmaxf(sqrtf(nn) * norm_o, EPS);
        float hinge  = fmaxf(0.f, MARGIN - dp / den_p + dn / den_n);
        partials[i] = hinge;
    }
}

// Deterministic single-block reduction: fixed strided order per thread,
// then fixed-shape shfl/shared tree. Bit-stable across replays.
__global__ void reduce_kernel(const float* __restrict__ partials,
                              float* __restrict__ result, int B)
{
    __shared__ float sh[32];
    float s = 0.f;
    for (int k = threadIdx.x; k < B; k += blockDim.x) s += partials[k];

    #pragma unroll
    for (int off = 16; off > 0; off >>= 1)
        s += __shfl_xor_sync(0xFFFFFFFFu, s, off);

    if ((threadIdx.x & 31) == 0) sh[threadIdx.x >> 5] = s;
    __syncthreads();

    if (threadIdx.x < 32) {
        int nwarps = blockDim.x >> 5;
        float v = (threadIdx.x < nwarps) ? sh[threadIdx.x] : 0.f;
        #pragma unroll
        for (int off = 16; off > 0; off >>= 1)
            v += __shfl_xor_sync(0xFFFFFFFFu, v, off);
        if (threadIdx.x == 0) result[0] = v / (float)B;
    }
}

extern "C" void kernel_launch(void* const* d_in, const int* in_sizes, int n_in,
                              void* d_out, int out_size)
{
    const float*     out = (const float*)d_in[0];       // output [B, D] f32
    const float*     tgt = (const float*)d_in[1];       // target [B, D] f32
    const long long* neg = (const long long*)d_in[2];   // neg_idx [B] i64

    const int B = in_sizes[2];
    const int D = in_sizes[0] / B;

    float* partials = nullptr;
    cudaGetSymbolAddress((void**)&partials, g_partials);

    const int threads = 256;                    // 8 warps = 8 rows per block
    const int rows_per_block = threads >> 5;
    const int grid = (B + rows_per_block - 1) / rows_per_block;

    hinge_rows_kernel<<<grid, threads>>>(out, tgt, neg, partials, B, D);
    reduce_kernel<<<1, 1024>>>(partials, (float*)d_out, B);
}

// round 12
// speedup vs baseline: 1.2554x; 1.2554x over previous
#include <cuda_runtime.h>

#define MARGIN 1.0f
#define EPS 1e-6f

// Scratch (no device allocation allowed). B=16384, 8 rows/block -> 2048 blocks.
__device__ float        g_partials[4096];
__device__ unsigned int g_ticket = 0;

// One warp per row, 8 warps per block. Fused grid-wide deterministic reduction:
// last block (ticket) reduces all per-block partials in fixed order.
__global__ void hinge_fused_kernel(const float* __restrict__ out,
                                   const float* __restrict__ tgt,
                                   const long long* __restrict__ neg,
                                   float* __restrict__ result,
                                   int B, int D, int nblocks)
{
    __shared__ float sh[8];
    __shared__ bool  is_last;

    const int warp = threadIdx.x >> 5;
    const int lane = threadIdx.x & 31;
    const int row  = blockIdx.x * 8 + warp;

    float hinge = 0.f;
    if (row < B) {
        long long j = ((long long)row + 1 + neg[row]) % (long long)B;

        const float4* __restrict__ o4 = (const float4*)(out + (size_t)row * D);
        const float4* __restrict__ t4 = (const float4*)(tgt + (size_t)row * D);
        const float4* __restrict__ n4 = (const float4*)(tgt + (size_t)j   * D);

        float dp = 0.f, dn = 0.f, no = 0.f, nt = 0.f, nn = 0.f;

        const int nv = D >> 2;  // D=1024 -> 256 float4 per row, 8 per lane
        #pragma unroll 8
        for (int k = lane; k < nv; k += 32) {
            float4 o = __ldcs(&o4[k]);   // streaming: output read exactly once
            float4 t = t4[k];            // default: keep target hot in L2 (gather reuse)
            float4 g = n4[k];
            dp += o.x * t.x + o.y * t.y + o.z * t.z + o.w * t.w;
            dn += o.x * g.x + o.y * g.y + o.z * g.z + o.w * g.w;
            no += o.x * o.x + o.y * o.y + o.z * o.z + o.w * o.w;
            nt += t.x * t.x + t.y * t.y + t.z * t.z + t.w * t.w;
            nn += g.x * g.x + g.y * g.y + g.z * g.z + g.w * g.w;
        }

        #pragma unroll
        for (int off = 16; off > 0; off >>= 1) {
            dp += __shfl_xor_sync(0xFFFFFFFFu, dp, off);
            dn += __shfl_xor_sync(0xFFFFFFFFu, dn, off);
            no += __shfl_xor_sync(0xFFFFFFFFu, no, off);
            nt += __shfl_xor_sync(0xFFFFFFFFu, nt, off);
            nn += __shfl_xor_sync(0xFFFFFFFFu, nn, off);
        }

        if (lane == 0) {
            float norm_o = sqrtf(no);
            float den_p  = fmaxf(sqrtf(nt) * norm_o, EPS);
            float den_n  = fmaxf(sqrtf(nn) * norm_o, EPS);
            hinge = fmaxf(0.f, MARGIN - dp / den_p + dn / den_n);
        }
    }

    if (lane == 0) sh[warp] = hinge;
    __syncthreads();

    // Thread 0: fixed-order block sum, publish partial, take a ticket.
    if (threadIdx.x == 0) {
        float bs = 0.f;
        #pragma unroll
        for (int w = 0; w < 8; w++) bs += sh[w];
        g_partials[blockIdx.x] = bs;
        __threadfence();
        unsigned int t = atomicAdd(&g_ticket, 1u);
        is_last = (t == (unsigned int)(nblocks - 1));
    }
    __syncthreads();

    if (!is_last) return;

    // Last block: deterministic fixed-order reduction of all partials (L2-hot).
    float s = 0.f;
    for (int k = threadIdx.x; k < nblocks; k += blockDim.x) s += g_partials[k];

    #pragma unroll
    for (int off = 16; off > 0; off >>= 1)
        s += __shfl_xor_sync(0xFFFFFFFFu, s, off);

    if (lane == 0) sh[warp] = s;
    __syncthreads();

    if (threadIdx.x == 0) {
        float tot = 0.f;
        #pragma unroll
        for (int w = 0; w < 8; w++) tot += sh[w];
        result[0] = tot / (float)B;
        g_ticket = 0;   // reset for next graph replay
    }
}

extern "C" void kernel_launch(void* const* d_in, const int* in_sizes, int n_in,
                              void* d_out, int out_size)
{
    const float*     out = (const float*)d_in[0];       // output [B, D] f32
    const float*     tgt = (const float*)d_in[1];       // target [B, D] f32
    const long long* neg = (const long long*)d_in[2];   // neg_idx [B] i64

    const int B = in_sizes[2];
    const int D = in_sizes[0] / B;

    const int threads = 256;                 // 8 warps = 8 rows per block
    const int grid = (B + 7) / 8;            // 2048 blocks for B=16384

    hinge_fused_kernel<<<grid, threads>>>(out, tgt, neg, (float*)d_out, B, D, grid);
}